// round 3
// baseline (speedup 1.0000x reference)
#include <cuda_runtime.h>
#include <cstdint>

#define NN 100000
#define EE 3200000
#define DD 64
#define SCAN_B 256
#define NBLK ((NN + SCAN_B - 1) / SCAN_B)   // 391

// Static scratch (no allocation allowed)
__device__ int   g_deg[NN];
__device__ float g_dinv[NN];
__device__ int   g_ptr[NN + 1];
__device__ int   g_bsum[NBLK];
__device__ int   g_boff[NBLK];
__device__ int   g_fill[NN];
__device__ __align__(16) int2  g_csr[EE];      // {src_row, bitcast(norm)}
__device__ __align__(16) float g_xa[NN * DD];
__device__ __align__(16) float g_xb[NN * DD];

// ---------------- preprocessing ----------------

__global__ void zero_counts_kernel() {
    int i = blockIdx.x * blockDim.x + threadIdx.x;
    if (i < NN) { g_deg[i] = 0; g_fill[i] = 0; }
}

__global__ void count_deg_kernel(const int* __restrict__ col32) {
    int e = blockIdx.x * blockDim.x + threadIdx.x;
    if (e < EE) {
        int c = col32[e];
        if (c >= 0 && c < NN) atomicAdd(&g_deg[c], 1);
    }
}

__global__ void dinv_kernel() {
    int i = blockIdx.x * blockDim.x + threadIdx.x;
    if (i < NN) {
        int d = g_deg[i];
        g_dinv[i] = (d > 0) ? rsqrtf((float)d) : 0.0f;
    }
}

// scan level 1: per-block exclusive scan of g_deg into g_ptr, block total -> g_bsum
__global__ void scan1_kernel() {
    __shared__ int s[SCAN_B];
    int tid = threadIdx.x;
    int gid = blockIdx.x * SCAN_B + tid;
    int v = (gid < NN) ? g_deg[gid] : 0;
    s[tid] = v;
    __syncthreads();
    #pragma unroll
    for (int off = 1; off < SCAN_B; off <<= 1) {
        int t = (tid >= off) ? s[tid - off] : 0;
        __syncthreads();
        s[tid] += t;
        __syncthreads();
    }
    if (gid < NN) g_ptr[gid] = s[tid] - v;    // exclusive
    if (tid == SCAN_B - 1) g_bsum[blockIdx.x] = s[tid];
}

// scan level 2: one block scans the 391 block sums
__global__ void scan2_kernel() {
    __shared__ int s[512];
    int tid = threadIdx.x;
    int v = (tid < NBLK) ? g_bsum[tid] : 0;
    s[tid] = v;
    __syncthreads();
    #pragma unroll
    for (int off = 1; off < 512; off <<= 1) {
        int t = (tid >= off) ? s[tid - off] : 0;
        __syncthreads();
        s[tid] += t;
        __syncthreads();
    }
    if (tid < NBLK) g_boff[tid] = s[tid] - v; // exclusive
    if (tid == NBLK - 1) g_ptr[NN] = s[tid];  // grand total
}

// scan level 3: add block offsets
__global__ void scan3_kernel() {
    int gid = blockIdx.x * SCAN_B + threadIdx.x;
    if (gid < NN) g_ptr[gid] += g_boff[blockIdx.x];
}

// fill CSR: bucket edges by target col; payload = {src, norm}
__global__ void fill_kernel(const int* __restrict__ row32,
                            const int* __restrict__ col32) {
    int e = blockIdx.x * blockDim.x + threadIdx.x;
    if (e < EE) {
        int r = row32[e];
        int c = col32[e];
        if (r >= 0 && r < NN && c >= 0 && c < NN) {
            float nrm = g_dinv[r] * g_dinv[c];
            int pos = atomicAdd(&g_fill[c], 1);
            g_csr[g_ptr[c] + pos] = make_int2(r, __float_as_int(nrm));
        }
    }
}

// out = emb (initialize accumulator)
__global__ void init_kernel(const float* __restrict__ emb, float* __restrict__ out) {
    int i = blockIdx.x * blockDim.x + threadIdx.x;
    if (i < NN * DD) out[i] = emb[i];
}

// ---------------- per-layer gather ----------------
// One warp per node. Lane t owns feature cols {t, t+32}.
// x_new[node] = sum_e norm_e * xin[src_e]; out[node] = (out[node] + x_new)*scale.
__global__ __launch_bounds__(256) void gather_kernel(const float* __restrict__ xin,
                                                     float* __restrict__ xout,
                                                     float* __restrict__ out,
                                                     float scale) {
    int warp = (blockIdx.x * blockDim.x + threadIdx.x) >> 5;
    int lane = threadIdx.x & 31;
    if (warp >= NN) return;
    int node  = warp;
    int start = g_ptr[node];
    int end   = g_ptr[node + 1];

    float acc0 = 0.0f, acc1 = 0.0f;
    for (int base = start; base < end; base += 32) {
        int n = end - base;
        if (n > 32) n = 32;
        int2 ed;
        if (lane < n) ed = __ldg(&g_csr[base + lane]);
        #pragma unroll 8
        for (int k = 0; k < n; k++) {
            int   src = __shfl_sync(0xffffffffu, ed.x, k);
            float nrm = __int_as_float(__shfl_sync(0xffffffffu, ed.y, k));
            const float* sp = xin + (long long)src * DD;
            acc0 = fmaf(nrm, __ldg(sp + lane),      acc0);
            acc1 = fmaf(nrm, __ldg(sp + lane + 32), acc1);
        }
    }

    if (xout) {
        float* xo = xout + (long long)node * DD;
        xo[lane]      = acc0;
        xo[lane + 32] = acc1;
    }
    float* op = out + (long long)node * DD;
    op[lane]      = (op[lane]      + acc0) * scale;
    op[lane + 32] = (op[lane + 32] + acc1) * scale;
}

// ---------------- launch ----------------

extern "C" void kernel_launch(void* const* d_in, const int* in_sizes, int n_in,
                              void* d_out, int out_size) {
    const float* emb = (const float*)d_in[0];
    const int* edge  = (const int*)d_in[1];   // [2, EE] int32
    const int* row32 = edge;
    const int* col32 = edge + EE;
    float* out = (float*)d_out;

    const int T = 256;
    int gN  = (NN + T - 1) / T;
    int gE  = (EE + T - 1) / T;
    int gND = (NN * DD + T - 1) / T;
    int gG  = (NN * 32 + T - 1) / T;   // one warp per node

    // CSR build
    zero_counts_kernel<<<gN, T>>>();
    count_deg_kernel<<<gE, T>>>(col32);
    dinv_kernel<<<gN, T>>>();
    scan1_kernel<<<NBLK, SCAN_B>>>();
    scan2_kernel<<<1, 512>>>();
    scan3_kernel<<<NBLK, SCAN_B>>>();
    fill_kernel<<<gE, T>>>(row32, col32);

    // acc init
    init_kernel<<<gND, T>>>(emb, out);

    // Layer 1: emb -> g_xa, out += x1
    gather_kernel<<<gG, T>>>(emb, g_xa, out, 1.0f);
    // Layer 2: g_xa -> g_xb, out += x2
    gather_kernel<<<gG, T>>>(g_xa, g_xb, out, 1.0f);
    // Layer 3: g_xb -> (discard), out = (out + x3)/4
    gather_kernel<<<gG, T>>>(g_xb, nullptr, out, 0.25f);
}